// round 2
// baseline (speedup 1.0000x reference)
#include <cuda_runtime.h>
#include <stdint.h>

// ---------------- problem constants ----------------
#define TSTEPS 512
#define BSZ    256
#define NIN    128
#define NHID   512
#define NOUT   10
#define KTOT   1152
#define DTc    0.042f
#define GAMc   2.7f
#define EPSc   4.7f

// ---------------- kernel config ----------------
#define NCTA    128          // 8 (M tiles of 32) x 16 (N tiles of 32)
#define THREADS 256
#define CHUNK   288          // K elements staged per cp.async round
#define NCHUNK  4            // 4 * 288 = 1152
#define KB_PER_CHUNK 36      // 288/8 k8-blocks
#define KB_PER_WARP  18      // kh split in 2

// smem word layout
#define WS_WORDS (144*256)   // 36864 : W slice [kb(144)][n(32)][kk(8)]
#define BIAS_OFF WS_WORDS    // 32 words
#define AB0_OFF  (WS_WORDS + 32)
#define AB_WORDS (KB_PER_CHUNK*256)   // 9216 : A chunk [kb(36)][r(32)][kk(8)]
#define AB1_OFF  (AB0_OFF + AB_WORDS)
#define SMEM_WORDS (AB1_OFF + AB_WORDS)
#define SMEM_BYTES (SMEM_WORDS*4)     // 221,312 B

// ---------------- device scratch ----------------
__device__ float    g_hy[2][BSZ*NHID];
__device__ float    g_hz[2][BSZ*NHID];
__device__ unsigned g_bar[520];       // per-step barrier counters (monotonic)

// ---------------- helpers ----------------
__device__ __forceinline__ float fast_tanh(float v) {
    float e = __expf(2.0f * v);              // inf / 0 saturate correctly
    return 1.0f - __fdividef(2.0f, e + 1.0f);
}

__device__ __forceinline__ void mma_tf32(float* d,
                                         unsigned a0, unsigned a1, unsigned a2, unsigned a3,
                                         unsigned b0, unsigned b1) {
    asm volatile("mma.sync.aligned.m16n8k8.row.col.f32.tf32.tf32.f32 "
                 "{%0,%1,%2,%3}, {%4,%5,%6,%7}, {%8,%9}, {%0,%1,%2,%3};"
                 : "+f"(d[0]), "+f"(d[1]), "+f"(d[2]), "+f"(d[3])
                 : "r"(a0), "r"(a1), "r"(a2), "r"(a3), "r"(b0), "r"(b1));
}

__device__ __forceinline__ unsigned to_tf32(float f) {
    unsigned u;
    asm("cvt.rna.tf32.f32 %0, %1;" : "=r"(u) : "f"(f));
    return u;
}

// grid-wide barrier; counter g_bar[idx] used exactly once per launch
__device__ __forceinline__ void grid_bar(int idx) {
    __syncthreads();
    if (threadIdx.x == 0) {
        atomicAdd(&g_bar[idx], 1u);
        volatile unsigned* vp = &g_bar[idx];
        while (*vp < (unsigned)NCTA) { }
        __threadfence();
    }
    __syncthreads();
}

// stage one K-chunk of inp = [x_t | hz | hy] for this CTA's 32 batch rows.
// smem layout word = kb*256 + r*8 + kk  (straight local k within k8 block)
__device__ __forceinline__ void stage_chunk(float* dst, int ch, int t, int mi,
                                            const float* __restrict__ x,
                                            const float* __restrict__ hz_cur,
                                            const float* __restrict__ hy_cur) {
    unsigned dbase = (unsigned)__cvta_generic_to_shared(dst);
    const int tid = threadIdx.x;
#pragma unroll
    for (int j = 0; j < 9; ++j) {            // 9*256 = 2304 = 36 kb * 32 r * 2 q
        int i  = tid + j * 256;
        int q  = i & 1;
        int r  = (i >> 1) & 31;
        int kb = i >> 6;
        int kg = ch * CHUNK + kb * 8 + q * 4;  // global k of this 16B piece
        int brow = mi * 32 + r;
        const float* src;
        if (kg < NIN)             src = x      + ((size_t)t * BSZ + brow) * NIN  + kg;
        else if (kg < NIN + NHID) src = hz_cur + (size_t)brow * NHID + (kg - NIN);
        else                      src = hy_cur + (size_t)brow * NHID + (kg - NIN - NHID);
        unsigned daddr = dbase + (unsigned)((kb * 256 + r * 8 + q * 4) << 2);
        asm volatile("cp.async.cg.shared.global [%0], [%1], 16;" :: "r"(daddr), "l"(src));
    }
}

// ---------------- persistent recurrence kernel ----------------
__global__ void __launch_bounds__(THREADS, 1)
cornn_persist(const float* __restrict__ x, const float* __restrict__ W,
              const float* __restrict__ bias) {
    extern __shared__ float smem[];
    float* Bsh = smem + BIAS_OFF;

    const int tid  = threadIdx.x;
    const int cta  = blockIdx.x;
    const int mi   = cta >> 4;            // 0..7
    const int ni   = cta & 15;            // 0..15
    const int lane = tid & 31;
    const int warp = tid >> 5;
    const int wm   = warp & 1;            // m16 slab
    const int wn   = (warp >> 1) & 1;     // n16 slab
    const int kh   = warp >> 2;           // k-half

    // one-time: W slice -> smem, tf32-rounded.  layout [kb][n][kk]
    for (int i = tid; i < WS_WORDS; i += THREADS) {
        int n  = i & 31;
        int kk = (i >> 5) & 7;
        int kb = i >> 8;
        float w = W[(size_t)(kb * 8 + kk) * NHID + ni * 32 + n];
        smem[kb * 256 + n * 8 + kk] = __uint_as_float(to_tf32(w));
    }
    if (tid < 32) Bsh[tid] = bias[ni * 32 + tid];

    // zero initial state patch (buffer 0)
    for (int i = tid; i < 1024; i += THREADS) {
        int r = i >> 5, c = i & 31;
        size_t idx = (size_t)(mi * 32 + r) * NHID + ni * 32 + c;
        g_hz[0][idx] = 0.0f;
        g_hy[0][idx] = 0.0f;
    }
    grid_bar(0);

    // register-resident state for kh0 warps (8 elements per thread)
    float hyr[8], hzr[8];
#pragma unroll
    for (int i = 0; i < 8; ++i) { hyr[i] = 0.0f; hzr[i] = 0.0f; }

    const int aoff = kh * KB_PER_WARP * 256 + (wm * 16 + (lane >> 2)) * 8 + (lane & 3) * 2;
    const int boff = (wn * 16 + (lane >> 2)) * 8 + (lane & 3) * 2;

    for (int t = 0; t < TSTEPS; ++t) {
        const int rb = t & 1, wb = rb ^ 1;
        const float* hzc = g_hz[rb];
        const float* hyc = g_hy[rb];

        float acc[2][4];
#pragma unroll
        for (int f = 0; f < 2; ++f)
#pragma unroll
            for (int c = 0; c < 4; ++c) acc[f][c] = 0.0f;

        stage_chunk(smem + AB0_OFF, 0, t, mi, x, hzc, hyc);
        asm volatile("cp.async.commit_group;");

        for (int ch = 0; ch < NCHUNK; ++ch) {
            if (ch < 3) {
                stage_chunk(smem + (((ch + 1) & 1) ? AB1_OFF : AB0_OFF), ch + 1, t, mi, x, hzc, hyc);
                asm volatile("cp.async.commit_group;");
                asm volatile("cp.async.wait_group 1;");
            } else {
                asm volatile("cp.async.wait_group 0;");
            }
            __syncthreads();

            const float* Ab = smem + ((ch & 1) ? AB1_OFF : AB0_OFF);
            const float* Wb = smem + (ch * KB_PER_CHUNK + kh * KB_PER_WARP) * 256;
#pragma unroll
            for (int j = 0; j < KB_PER_WARP; ++j) {
                float2 a_lo = *reinterpret_cast<const float2*>(Ab + aoff + j * 256);
                float2 a_hi = *reinterpret_cast<const float2*>(Ab + aoff + j * 256 + 64);
                unsigned a0 = to_tf32(a_lo.x);
                unsigned a1 = to_tf32(a_hi.x);
                unsigned a2 = to_tf32(a_lo.y);
                unsigned a3 = to_tf32(a_hi.y);
                float2 b0 = *reinterpret_cast<const float2*>(Wb + boff + j * 256);
                float2 b1 = *reinterpret_cast<const float2*>(Wb + boff + j * 256 + 64);
                mma_tf32(acc[0], a0, a1, a2, a3, __float_as_uint(b0.x), __float_as_uint(b0.y));
                mma_tf32(acc[1], a0, a1, a2, a3, __float_as_uint(b1.x), __float_as_uint(b1.y));
            }
            __syncthreads();
        }

        // ---- epilogue: combine k-halves, tanh, state update, publish ----
        float* ex = smem + AB0_OFF;   // reuse chunk buffer 0 as exchange
        const int r0 = wm * 16 + (lane >> 2);
        const int c0 = wn * 16 + (lane & 3) * 2;
        if (kh == 1) {
#pragma unroll
            for (int f = 0; f < 2; ++f) {
                int c = c0 + f * 8;
                *reinterpret_cast<float2*>(&ex[r0 * 32 + c])       = make_float2(acc[f][0], acc[f][1]);
                *reinterpret_cast<float2*>(&ex[(r0 + 8) * 32 + c]) = make_float2(acc[f][2], acc[f][3]);
            }
        }
        __syncthreads();
        if (kh == 0) {
#pragma unroll
            for (int f = 0; f < 2; ++f) {
                int c = c0 + f * 8;
#pragma unroll
                for (int half = 0; half < 2; ++half) {
                    int row = r0 + half * 8;
                    float v0 = acc[f][half * 2 + 0] + ex[row * 32 + c];
                    float v1 = acc[f][half * 2 + 1] + ex[row * 32 + c + 1];
                    float pre0 = fast_tanh(v0 + Bsh[c]);
                    float pre1 = fast_tanh(v1 + Bsh[c + 1]);
                    int s = f * 4 + half * 2;
                    float hz0 = hzr[s],     hy0 = hyr[s];
                    float hz1 = hzr[s + 1], hy1 = hyr[s + 1];
                    hz0 += DTc * (pre0 - GAMc * hy0 - EPSc * hz0);  hy0 += DTc * hz0;
                    hz1 += DTc * (pre1 - GAMc * hy1 - EPSc * hz1);  hy1 += DTc * hz1;
                    hzr[s] = hz0; hyr[s] = hy0; hzr[s + 1] = hz1; hyr[s + 1] = hy1;
                    size_t gi = (size_t)(mi * 32 + row) * NHID + ni * 32 + c;
                    __stcg(reinterpret_cast<float2*>(&g_hz[wb][gi]), make_float2(hz0, hz1));
                    __stcg(reinterpret_cast<float2*>(&g_hy[wb][gi]), make_float2(hy0, hy1));
                }
            }
        }
        __threadfence();
        grid_bar(t + 1);
    }
}

// ---------------- prologue: zero barrier counters ----------------
__global__ void zero_bar_kernel() {
    for (int i = threadIdx.x; i < 520; i += blockDim.x) g_bar[i] = 0u;
}

// ---------------- output GEMM: out = hy_final @ Wout + bout ----------------
// final state is in buffer 0 (t=511 wrote wb = 1 - (511&1) = 0)
__global__ void out_kernel(const float* __restrict__ Wout,
                           const float* __restrict__ bout,
                           float* __restrict__ out) {
    int b = blockIdx.x;
    int lane = threadIdx.x;
    const float* h = g_hy[0] + (size_t)b * NHID;
    float acc[NOUT];
#pragma unroll
    for (int j = 0; j < NOUT; ++j) acc[j] = 0.0f;
    for (int k = lane; k < NHID; k += 32) {
        float hv = h[k];
#pragma unroll
        for (int j = 0; j < NOUT; ++j) acc[j] += hv * Wout[k * NOUT + j];
    }
#pragma unroll
    for (int j = 0; j < NOUT; ++j) {
#pragma unroll
        for (int o = 16; o > 0; o >>= 1)
            acc[j] += __shfl_xor_sync(0xffffffffu, acc[j], o);
    }
    if (lane == 0) {
#pragma unroll
        for (int j = 0; j < NOUT; ++j) out[b * NOUT + j] = acc[j] + bout[j];
    }
}

// ---------------- launch ----------------
extern "C" void kernel_launch(void* const* d_in, const int* in_sizes, int n_in,
                              void* d_out, int out_size) {
    (void)in_sizes; (void)n_in; (void)out_size;
    const float* x    = (const float*)d_in[0];
    const float* W    = (const float*)d_in[1];
    const float* b    = (const float*)d_in[2];
    const float* Wout = (const float*)d_in[3];
    const float* bout = (const float*)d_in[4];
    float* out = (float*)d_out;

    cudaFuncSetAttribute(cornn_persist, cudaFuncAttributeMaxDynamicSharedMemorySize, SMEM_BYTES);

    zero_bar_kernel<<<1, 256>>>();
    cornn_persist<<<NCTA, THREADS, SMEM_BYTES>>>(x, W, b);
    out_kernel<<<BSZ, 32>>>(Wout, bout, out);
}

// round 3
// speedup vs baseline: 1.2951x; 1.2951x over previous
#include <cuda_runtime.h>
#include <stdint.h>

// ---------------- problem constants ----------------
#define TSTEPS 512
#define BSZ    256
#define NIN    128
#define NHID   512
#define NOUT   10
#define DTc    0.042f
#define GAMc   2.7f
#define EPSc   4.7f

// ---------------- kernel config ----------------
#define NCTA    128          // 8 M-tiles(32) x 16 N-tiles(32)
#define THREADS 256          // 8 warps: kh split, each warp = m32n32, 18 k8-blocks
#define NKB     144          // 1152/8 k8-blocks total
#define JPW     18           // k8-blocks per warp (strided: kb = 8j + warp)

// smem layout (words)
#define AS_WORDS  (NKB*256)          // 36864 : A panel [kb][r(32)][kk(8)] ; also W staging at init
#define PART_OFF  AS_WORDS
#define PART_STRIDE 36               // padded row stride for partial tiles
#define PART_WORDS (8*32*PART_STRIDE) // 9216
#define BIAS_OFF  (PART_OFF + PART_WORDS)
#define SMEM_WORDS (BIAS_OFF + 32)
#define SMEM_BYTES (SMEM_WORDS*4)    // 184448 B

// ---------------- device scratch ----------------
__device__ float    g_hy[2][BSZ*NHID];
__device__ float    g_hz[2][BSZ*NHID];
__device__ unsigned g_bar[513];

// ---------------- helpers ----------------
__device__ __forceinline__ float fast_tanh(float v) {
    float e = __expf(2.0f * v);
    return 1.0f - __fdividef(2.0f, e + 1.0f);
}
__device__ __forceinline__ unsigned to_tf32(float f) {
    unsigned u;
    asm("cvt.rna.tf32.f32 %0, %1;" : "=r"(u) : "f"(f));
    return u;
}
__device__ __forceinline__ void mma_tf32(float* d,
                                         unsigned a0, unsigned a1, unsigned a2, unsigned a3,
                                         unsigned b0, unsigned b1) {
    asm volatile("mma.sync.aligned.m16n8k8.row.col.f32.tf32.tf32.f32 "
                 "{%0,%1,%2,%3}, {%4,%5,%6,%7}, {%8,%9}, {%0,%1,%2,%3};"
                 : "+f"(d[0]), "+f"(d[1]), "+f"(d[2]), "+f"(d[3])
                 : "r"(a0), "r"(a1), "r"(a2), "r"(a3), "r"(b0), "r"(b1));
}
__device__ __forceinline__ void bar_arrive(int idx) {
    asm volatile("red.release.gpu.global.add.u32 [%0], 1;" :: "l"(&g_bar[idx]) : "memory");
}
__device__ __forceinline__ void bar_poll(int idx) {
    unsigned v;
    do {
        asm volatile("ld.acquire.gpu.global.u32 %0, [%1];" : "=r"(v) : "l"(&g_bar[idx]) : "memory");
    } while (v < (unsigned)NCTA);
}

// stage k8-blocks [kb0,kb1) of inp=[x_t|hz|hy] for batch rows mi*32..+31
__device__ __forceinline__ void stage_kbs(float* As, int kb0, int kb1, int t, int mi,
                                          const float* __restrict__ x,
                                          const float* __restrict__ hz,
                                          const float* __restrict__ hy) {
    unsigned dbase = (unsigned)__cvta_generic_to_shared(As);
    for (int ii = kb0 * 64 + threadIdx.x; ii < kb1 * 64; ii += THREADS) {
        int q  = ii & 1;
        int r  = (ii >> 1) & 31;
        int kb = ii >> 6;
        int kg = kb * 8 + q * 4;
        int brow = mi * 32 + r;
        const float* src;
        if (kg < NIN)             src = x  + ((size_t)t * BSZ + brow) * NIN + kg;
        else if (kg < NIN + NHID) src = hz + (size_t)brow * NHID + (kg - NIN);
        else                      src = hy + (size_t)brow * NHID + (kg - NIN - NHID);
        unsigned da = dbase + (unsigned)((kb * 256 + r * 8 + q * 4) << 2);
        asm volatile("cp.async.cg.shared.global [%0], [%1], 16;" :: "r"(da), "l"(src));
    }
}

#define COMMIT()      asm volatile("cp.async.commit_group;")
#define WAITG(n)      asm volatile("cp.async.wait_group %0;" :: "n"(n))

// compute k8-blocks j in [J0,J1) for this warp (kb = 8j + warp); J0/J1 compile-time
#define COMPUTE_RANGE(J0, J1)                                              \
    _Pragma("unroll")                                                      \
    for (int j = (J0); j < (J1); ++j) {                                    \
        const float* ab = As + (j * 8 + warp) * 256 + arow;                \
        float2 p0 = *(const float2*)(ab);                                  \
        float2 p1 = *(const float2*)(ab + 64);                             \
        float2 p2 = *(const float2*)(ab + 128);                            \
        float2 p3 = *(const float2*)(ab + 192);                            \
        unsigned a0 = to_tf32(p0.x), a2 = to_tf32(p0.y);                   \
        unsigned a1 = to_tf32(p1.x), a3 = to_tf32(p1.y);                   \
        unsigned a4 = to_tf32(p2.x), a6 = to_tf32(p2.y);                   \
        unsigned a5 = to_tf32(p3.x), a7 = to_tf32(p3.y);                   \
        _Pragma("unroll")                                                  \
        for (int nf = 0; nf < 4; ++nf) {                                   \
            mma_tf32(acc0[nf], a0, a1, a2, a3, wb0[j][nf], wb1[j][nf]);    \
            mma_tf32(acc1[nf], a4, a5, a6, a7, wb0[j][nf], wb1[j][nf]);    \
        }                                                                  \
    }

// ---------------- single persistent kernel ----------------
__global__ void __launch_bounds__(THREADS, 1)
cornn_persist(const float* __restrict__ x, const float* __restrict__ W,
              const float* __restrict__ bias,
              const float* __restrict__ Wout, const float* __restrict__ bout,
              float* __restrict__ out) {
    extern __shared__ float smem[];
    float* As   = smem;
    float* Part = smem + PART_OFF;
    float* Bsh  = smem + BIAS_OFF;

    const int tid  = threadIdx.x;
    const int cta  = blockIdx.x;
    const int mi   = cta >> 4;            // 0..7
    const int ni   = cta & 15;            // 0..15
    const int lane = tid & 31;
    const int warp = tid >> 5;            // = kh slice 0..7
    const int arow = (lane >> 2) * 8 + (lane & 3) * 2;

    // ---- init: stage W slice into As (coalesced), then load B frags to regs ----
    for (int i = tid; i < AS_WORDS; i += THREADS) {
        int n  = i & 31;
        int kk = (i >> 5) & 7;
        int kb = i >> 8;
        smem[kb * 256 + n * 8 + kk] = W[(size_t)(kb * 8 + kk) * NHID + ni * 32 + n];
    }
    if (tid < 32) Bsh[tid] = bias[ni * 32 + tid];
    __syncthreads();

    // B fragments: warp owns kb = 8j + warp; b0=B[2c][n], b1=B[2c+1][n] (k-perm matches A)
    unsigned wb0[JPW][4], wb1[JPW][4];
#pragma unroll
    for (int j = 0; j < JPW; ++j) {
        const float* bs = As + (j * 8 + warp) * 256 + (lane >> 2) * 8 + (lane & 3) * 2;
#pragma unroll
        for (int nf = 0; nf < 4; ++nf) {
            float2 v = *(const float2*)(bs + nf * 64);
            wb0[j][nf] = to_tf32(v.x);
            wb1[j][nf] = to_tf32(v.y);
        }
    }
    __syncthreads();   // all frag reads done before As is reused as A panel

    // ---- zero initial state patch (buffer 0) ----
    for (int i = tid; i < 1024; i += THREADS) {
        int r = i >> 5, c = i & 31;
        size_t idx = (size_t)(mi * 32 + r) * NHID + ni * 32 + c;
        g_hz[0][idx] = 0.0f;
        g_hy[0][idx] = 0.0f;
    }
    __syncthreads();
    if (tid == 0) bar_arrive(0);

    // pre-stage x chunk for t=0 (independent of state)
    stage_kbs(As, 0, 16, 0, mi, x, g_hz[0], g_hy[0]);
    COMMIT();

    // register-resident state: this thread owns row (warp*4 + lane/8), cols (lane%8)*4..+3
    const int srow = warp * 4 + (lane >> 3);
    const int scol = (lane & 7) * 4;
    float hyr[4] = {0, 0, 0, 0}, hzr[4] = {0, 0, 0, 0};

    for (int t = 0; t < TSTEPS; ++t) {
        // wait for all CTAs' state from step t-1 (or init)
        if (tid == 0) bar_poll(t);
        __syncthreads();

        const int rb = t & 1, wbuf = rb ^ 1;
        const float* hzc = g_hz[rb];
        const float* hyc = g_hy[rb];

        // stage state chunks (group boundaries align to per-warp j ranges)
        stage_kbs(As, 16, 64, t, mi, x, hzc, hyc);  COMMIT();
        stage_kbs(As, 64, 112, t, mi, x, hzc, hyc); COMMIT();
        stage_kbs(As, 112, 144, t, mi, x, hzc, hyc); COMMIT();

        float acc0[4][4], acc1[4][4];
#pragma unroll
        for (int nf = 0; nf < 4; ++nf)
#pragma unroll
            for (int c = 0; c < 4; ++c) { acc0[nf][c] = 0.0f; acc1[nf][c] = 0.0f; }

        WAITG(3); __syncthreads(); COMPUTE_RANGE(0, 2);    // x part
        WAITG(2); __syncthreads(); COMPUTE_RANGE(2, 8);
        WAITG(1); __syncthreads(); COMPUTE_RANGE(8, 14);
        WAITG(0); __syncthreads(); COMPUTE_RANGE(14, 18);

        // ---- epilogue: each warp writes its 32x32 partial, then reduce 8 partials ----
        {
            float* P = Part + warp * (32 * PART_STRIDE);
            const int rr = lane >> 2;
            const int cc = (lane & 3) * 2;
#pragma unroll
            for (int nf = 0; nf < 4; ++nf) {
                int co = nf * 8 + cc;
                *(float2*)(P + rr * PART_STRIDE + co)        = make_float2(acc0[nf][0], acc0[nf][1]);
                *(float2*)(P + (rr + 8) * PART_STRIDE + co)  = make_float2(acc0[nf][2], acc0[nf][3]);
                *(float2*)(P + (rr + 16) * PART_STRIDE + co) = make_float2(acc1[nf][0], acc1[nf][1]);
                *(float2*)(P + (rr + 24) * PART_STRIDE + co) = make_float2(acc1[nf][2], acc1[nf][3]);
            }
        }
        __syncthreads();
        {
            float4 s = make_float4(0.f, 0.f, 0.f, 0.f);
#pragma unroll
            for (int p = 0; p < 8; ++p) {
                float4 v = *(const float4*)(Part + p * (32 * PART_STRIDE) + srow * PART_STRIDE + scol);
                s.x += v.x; s.y += v.y; s.z += v.z; s.w += v.w;
            }
            float pre0 = fast_tanh(s.x + Bsh[scol]);
            float pre1 = fast_tanh(s.y + Bsh[scol + 1]);
            float pre2 = fast_tanh(s.z + Bsh[scol + 2]);
            float pre3 = fast_tanh(s.w + Bsh[scol + 3]);
            hzr[0] += DTc * (pre0 - GAMc * hyr[0] - EPSc * hzr[0]);  hyr[0] += DTc * hzr[0];
            hzr[1] += DTc * (pre1 - GAMc * hyr[1] - EPSc * hzr[1]);  hyr[1] += DTc * hzr[1];
            hzr[2] += DTc * (pre2 - GAMc * hyr[2] - EPSc * hzr[2]);  hyr[2] += DTc * hzr[2];
            hzr[3] += DTc * (pre3 - GAMc * hyr[3] - EPSc * hzr[3]);  hyr[3] += DTc * hzr[3];
            size_t gi = (size_t)(mi * 32 + srow) * NHID + ni * 32 + scol;
            __stcg((float4*)&g_hz[wbuf][gi], make_float4(hzr[0], hzr[1], hzr[2], hzr[3]));
            __stcg((float4*)&g_hy[wbuf][gi], make_float4(hyr[0], hyr[1], hyr[2], hyr[3]));
        }
        __syncthreads();                       // all state stores done (CTA scope)
        if (tid == 0) bar_arrive(t + 1);       // release: publishes CTA's stores

        if (t + 1 < TSTEPS) {                  // pre-stage next x chunk while others arrive
            stage_kbs(As, 0, 16, t + 1, mi, x, hzc, hyc);
            COMMIT();
        }
    }

    // ---- final barrier, fused output GEMM, self-reset counters ----
    if (tid == 0) {
        bar_poll(TSTEPS);
        // last passer resets bar[512]; earlier indices safe to reset now
        unsigned old = atomicAdd(&g_bar[TSTEPS], 1u);
        if (old == 2u * NCTA - 2u) g_bar[TSTEPS] = 0u;
        for (int i = cta; i < TSTEPS; i += NCTA) g_bar[i] = 0u;
    }
    __syncthreads();

    // out = hy_final @ Wout + bout ; final hy is in buffer 0 (t=511 wrote wbuf=0)
    int gw = cta * 8 + warp;
    if (gw < BSZ) {
        const float* h = g_hy[0] + (size_t)gw * NHID;
        float acc[NOUT];
#pragma unroll
        for (int o = 0; o < NOUT; ++o) acc[o] = 0.0f;
        for (int k = lane; k < NHID; k += 32) {
            float hv = __ldcg(h + k);
#pragma unroll
            for (int o = 0; o < NOUT; ++o) acc[o] += hv * Wout[k * NOUT + o];
        }
#pragma unroll
        for (int o = 0; o < NOUT; ++o) {
#pragma unroll
            for (int s = 16; s > 0; s >>= 1)
                acc[o] += __shfl_xor_sync(0xffffffffu, acc[o], s);
        }
        if (lane == 0) {
#pragma unroll
            for (int o = 0; o < NOUT; ++o) out[gw * NOUT + o] = acc[o] + bout[o];
        }
    }
}

// ---------------- launch (single kernel -> ncu -s 5 -c 1 lands on it) ----------------
extern "C" void kernel_launch(void* const* d_in, const int* in_sizes, int n_in,
                              void* d_out, int out_size) {
    (void)in_sizes; (void)n_in; (void)out_size;
    const float* x    = (const float*)d_in[0];
    const float* W    = (const float*)d_in[1];
    const float* b    = (const float*)d_in[2];
    const float* Wout = (const float*)d_in[3];
    const float* bout = (const float*)d_in[4];
    float* out = (float*)d_out;

    cudaFuncSetAttribute(cornn_persist, cudaFuncAttributeMaxDynamicSharedMemorySize, SMEM_BYTES);
    cornn_persist<<<NCTA, THREADS, SMEM_BYTES>>>(x, W, b, Wout, bout, out);
}